// round 10
// baseline (speedup 1.0000x reference)
#include <cuda_runtime.h>
#include <cuda_bf16.h>

#define BEV_H 512
#define BEV_W 512
#define BEV_C 64
#define HW (BEV_H * BEV_W)   // 262144 = 2^18

// Scratch: last-writer pillar index per BEV cell (up to 8 batches).
__device__ int g_last[8 * HW];

// ---------------------------------------------------------------------------
// Scatter: last-occurrence-wins via atomicMax on pillar index.
// ---------------------------------------------------------------------------
__global__ void bev_scatter_kernel(const int* __restrict__ coords, int P) {
    int t = blockIdx.x * blockDim.x + threadIdx.x;
    int p0 = t * 4;
    if (p0 + 3 < P) {
        const int4* c4 = reinterpret_cast<const int4*>(coords + p0 * 3);
        int4 a  = __ldg(c4 + 0);  // b0 r0 c0 b1
        int4 bb = __ldg(c4 + 1);  // r1 c1 b2 r2
        int4 cc = __ldg(c4 + 2);  // c2 b3 r3 c3
        int bs[4] = {a.x, a.w, bb.z, cc.y};
        int rs[4] = {a.y, bb.x, bb.w, cc.z};
        int cs[4] = {a.z, bb.y, cc.x, cc.w};
#pragma unroll
        for (int k = 0; k < 4; k++) {
            int r = min(max(rs[k], 0), BEV_H - 1);
            int c = min(max(cs[k], 0), BEV_W - 1);
            atomicMax(&g_last[bs[k] * HW + r * BEV_W + c], p0 + k);
        }
    } else if (p0 < P) {
        for (int p = p0; p < P; p++) {
            int b = coords[3 * p + 0];
            int r = min(max(coords[3 * p + 1], 0), BEV_H - 1);
            int c = min(max(coords[3 * p + 2], 0), BEV_W - 1);
            atomicMax(&g_last[b * HW + r * BEV_W + c], p);
        }
    }
}

// ---------------------------------------------------------------------------
// Gather + transpose via cp.async (LDGSTS). Warp-autonomous, only __syncwarp.
// Warp owns 32 cells + two private 4KB buffers (one per 32-channel half).
//   Produce (per half h): lane (c8p=l&7, dp=l>>3); s=0..3, p=0..1:
//     cell=4*c8p+s, chunk jc=4p+dp; cp.async 16B from
//     feats[last*64 + h*32 + jc*4] -> buf_h[cell*32 + ((jc^c8p)<<2)] words.
//     Empty cell: src-size=0 -> HW zero-fill. Per instr: 8 rows x 64B = 8 wf.
//   Consume (per half): k=0..7: lane (d=l>>3, c8=l&7) reads channel 4k+d of
//     cells 4c8..4c8+3 via 4x LDS.32 at bank 4*(k^c8)+d (all 32 distinct,
//     conflict-free), then one STG.128 -> 4 channels x full 128B lines.
// All 16 cp.async issued up front (2 groups); queue hides global latency,
// so low occupancy (3 CTAs/SM from 64KB smem) is sufficient.
// ---------------------------------------------------------------------------
__global__ void __launch_bounds__(256) bev_gather_kernel(
    const float* __restrict__ feats,
    float* __restrict__ out) {
    extern __shared__ float sdyn[];      // 8 warps * 2048 floats = 64KB

    const int widx = threadIdx.x >> 5;
    const int l    = threadIdx.x & 31;
    const int c8   = l & 7;     // producer cell-group / consumer cell-quad
    const int d    = l >> 3;    // producer chunk sub-index / consumer channel

    const int wgid = blockIdx.x * 8 + widx;
    const int base = wgid * 32;              // first cell (32-aligned, in-batch)
    const int b    = base >> 18;
    const int pos  = base & (HW - 1);

    float* buf = sdyn + widx * 2048;         // [half][cell][chunk] words

    // Coalesced g_last load; per-cell values distributed via shuffle.
    const int myLast = __ldg(&g_last[base + l]);

    // ---- issue all cp.async: half h -> buf + h*1024 words ----
#pragma unroll
    for (int h = 0; h < 2; h++) {
        unsigned dst0;
        asm volatile("{ .reg .u64 t; cvta.to.shared.u64 t, %1; cvt.u32.u64 %0, t; }"
                     : "=r"(dst0) : "l"(buf + h * 1024));
#pragma unroll
        for (int s = 0; s < 4; s++) {
            const int lc  = __shfl_sync(0xffffffffu, myLast, 4 * c8 + s);
            const int lcc = max(lc, 0);
            const unsigned sz = (lc >= 0) ? 16u : 0u;
            const int cell = 4 * c8 + s;
            const float* src = feats + (size_t)lcc * BEV_C + h * 32;
#pragma unroll
            for (int p = 0; p < 2; p++) {
                const int jc = 4 * p + d;                       // chunk 0..7
                const unsigned dst =
                    dst0 + (unsigned)(cell * 128 + ((jc ^ c8) << 4));
                asm volatile(
                    "cp.async.ca.shared.global [%0], [%1], 16, %2;"
                    :: "r"(dst), "l"(src + jc * 4), "r"(sz) : "memory");
            }
        }
        asm volatile("cp.async.commit_group;" ::: "memory");
    }

    float* outb = out + (size_t)b * (BEV_C * HW) + pos;

    // ---- consume h0 ----
    asm volatile("cp.async.wait_group 1;" ::: "memory");
    __syncwarp();
#pragma unroll
    for (int k = 0; k < 8; k++) {
        const int wbase = ((k ^ c8) << 2) + d;   // chunk swizzle + channel byte
        float4 v;
        v.x = buf[(4 * c8 + 0) * 32 + wbase];
        v.y = buf[(4 * c8 + 1) * 32 + wbase];
        v.z = buf[(4 * c8 + 2) * 32 + wbase];
        v.w = buf[(4 * c8 + 3) * 32 + wbase];
        *reinterpret_cast<float4*>(outb + (size_t)(4 * k + d) * HW + 4 * c8) = v;
    }

    // ---- consume h1 ----
    asm volatile("cp.async.wait_group 0;" ::: "memory");
    __syncwarp();
#pragma unroll
    for (int k = 0; k < 8; k++) {
        const int wbase = 1024 + ((k ^ c8) << 2) + d;
        float4 v;
        v.x = buf[(4 * c8 + 0) * 32 + wbase];
        v.y = buf[(4 * c8 + 1) * 32 + wbase];
        v.z = buf[(4 * c8 + 2) * 32 + wbase];
        v.w = buf[(4 * c8 + 3) * 32 + wbase];
        *reinterpret_cast<float4*>(
            outb + (size_t)(32 + 4 * k + d) * HW + 4 * c8) = v;
    }
}

extern "C" void kernel_launch(void* const* d_in, const int* in_sizes, int n_in,
                              void* d_out, int out_size) {
    const float* feats  = (const float*)d_in[0];   // (P, 64) float32
    const int*   coords = (const int*)d_in[1];     // (P, 3) int32
    float*       out    = (float*)d_out;           // (B, 64, 512, 512) float32

    int P = in_sizes[0] / BEV_C;
    int B = out_size / (BEV_C * HW);
    if (B > 8) B = 8;
    int ncells = B * HW;

    // 1) init last-index grid to -1 (memset node; 0xFF bytes == -1 int)
    void* lastPtr = nullptr;
    cudaGetSymbolAddress(&lastPtr, g_last);
    cudaMemsetAsync(lastPtr, 0xFF, (size_t)ncells * sizeof(int), 0);

    // 2) scatter
    int nt = (P + 3) / 4;
    bev_scatter_kernel<<<(nt + 255) / 256, 256>>>(coords, P);

    // 3) gather + transpose: 32 cells per warp, 8 warps per CTA, 64KB smem
    static bool attr_set = false;
    if (!attr_set) {
        cudaFuncSetAttribute(bev_gather_kernel,
                             cudaFuncAttributeMaxDynamicSharedMemorySize,
                             64 * 1024);
        attr_set = true;
    }
    bev_gather_kernel<<<ncells / 256, 256, 64 * 1024>>>(feats, out);
}